// round 1
// baseline (speedup 1.0000x reference)
#include <cuda_runtime.h>
#include <math.h>

#define NT      16384
#define DMODEL  2048
#define NE      64
#define TPC     128     // tokens per CTA
#define KC      32      // K chunk

// 256 threads: tx = tid&15 (expert group of 4), ty = tid>>4 (token group of 8).
// Each thread owns an 8x4 accumulator tile (8 tokens x 4 experts).
__global__ __launch_bounds__(256, 2)
void gating_kernel(const float* __restrict__ x,
                   const float* __restrict__ W,
                   const float* __restrict__ b,
                   float* __restrict__ out)
{
    __shared__ float xs[TPC][KC];   // 16 KB
    __shared__ float ws[KC][NE];    // 8 KB

    const int tid = threadIdx.x;
    const int tx  = tid & 15;
    const int ty  = tid >> 4;
    const int t0  = blockIdx.x * TPC;

    float acc[8][4];
    #pragma unroll
    for (int i = 0; i < 8; i++)
        #pragma unroll
        for (int j = 0; j < 4; j++) acc[i][j] = 0.0f;

    for (int kc = 0; kc < DMODEL; kc += KC) {
        // load x tile: 128 rows x 32 floats = 1024 float4, 4 per thread
        #pragma unroll
        for (int l = 0; l < 4; l++) {
            int f   = tid + l * 256;
            int row = f >> 3;
            int c4  = f & 7;
            *(float4*)&xs[row][c4 * 4] =
                *(const float4*)&x[(size_t)(t0 + row) * DMODEL + kc + c4 * 4];
        }
        // load W tile: 32 rows x 64 floats = 512 float4, 2 per thread
        #pragma unroll
        for (int l = 0; l < 2; l++) {
            int f   = tid + l * 256;
            int row = f >> 4;
            int c4  = f & 15;
            *(float4*)&ws[row][c4 * 4] =
                *(const float4*)&W[(size_t)(kc + row) * NE + c4 * 4];
        }
        __syncthreads();

        #pragma unroll
        for (int kk = 0; kk < KC; kk += 4) {
            float4 wv[4];
            #pragma unroll
            for (int c = 0; c < 4; c++)
                wv[c] = *(float4*)&ws[kk + c][tx * 4];
            #pragma unroll
            for (int i = 0; i < 8; i++) {
                float4 xv = *(float4*)&xs[ty * 8 + i][kk];
                acc[i][0] = fmaf(xv.x, wv[0].x, acc[i][0]);
                acc[i][0] = fmaf(xv.y, wv[1].x, acc[i][0]);
                acc[i][0] = fmaf(xv.z, wv[2].x, acc[i][0]);
                acc[i][0] = fmaf(xv.w, wv[3].x, acc[i][0]);
                acc[i][1] = fmaf(xv.x, wv[0].y, acc[i][1]);
                acc[i][1] = fmaf(xv.y, wv[1].y, acc[i][1]);
                acc[i][1] = fmaf(xv.z, wv[2].y, acc[i][1]);
                acc[i][1] = fmaf(xv.w, wv[3].y, acc[i][1]);
                acc[i][2] = fmaf(xv.x, wv[0].z, acc[i][2]);
                acc[i][2] = fmaf(xv.y, wv[1].z, acc[i][2]);
                acc[i][2] = fmaf(xv.z, wv[2].z, acc[i][2]);
                acc[i][2] = fmaf(xv.w, wv[3].z, acc[i][2]);
                acc[i][3] = fmaf(xv.x, wv[0].w, acc[i][3]);
                acc[i][3] = fmaf(xv.y, wv[1].w, acc[i][3]);
                acc[i][3] = fmaf(xv.z, wv[2].w, acc[i][3]);
                acc[i][3] = fmaf(xv.w, wv[3].w, acc[i][3]);
            }
        }
        __syncthreads();
    }

    // bias
    float4 bv = *(const float4*)&b[tx * 4];
    #pragma unroll
    for (int i = 0; i < 8; i++) {
        acc[i][0] += bv.x; acc[i][1] += bv.y;
        acc[i][2] += bv.z; acc[i][3] += bv.w;
    }

    // Softmax + top-2 per token within 16-lane groups (width-16 shuffles
    // align with ty groups: lanes 0-15 <-> ty even, 16-31 <-> ty odd).
    float* out_tw  = out;                       // [NT,2]
    float* out_ti  = out + (size_t)NT * 2;      // [NT,2] indices as float
    float* out_w   = out + (size_t)NT * 4;      // [NT,NE]
    const unsigned FULL = 0xffffffffu;

    #pragma unroll
    for (int i = 0; i < 8; i++) {
        int t = t0 + ty * 8 + i;

        // max over 64
        float m = fmaxf(fmaxf(acc[i][0], acc[i][1]), fmaxf(acc[i][2], acc[i][3]));
        #pragma unroll
        for (int off = 8; off >= 1; off >>= 1)
            m = fmaxf(m, __shfl_xor_sync(FULL, m, off, 16));

        float e0 = __expf(acc[i][0] - m);
        float e1 = __expf(acc[i][1] - m);
        float e2 = __expf(acc[i][2] - m);
        float e3 = __expf(acc[i][3] - m);
        float s = e0 + e1 + e2 + e3;
        #pragma unroll
        for (int off = 8; off >= 1; off >>= 1)
            s += __shfl_xor_sync(FULL, s, off, 16);
        float inv = 1.0f / s;

        float w0 = e0 * inv, w1 = e1 * inv, w2 = e2 * inv, w3 = e3 * inv;

        // write full weights row (coalesced float4)
        float4 wout = make_float4(w0, w1, w2, w3);
        *(float4*)&out_w[(size_t)t * NE + tx * 4] = wout;

        // local top-2 among my 4 (lower index wins ties; descending)
        float v[4] = {w0, w1, w2, w3};
        float a1 = v[0]; int ai1 = tx * 4;
        float a2 = -1.0f; int ai2 = -1;
        #pragma unroll
        for (int j = 1; j < 4; j++) {
            float vv = v[j]; int vi = tx * 4 + j;
            if (vv > a1) { a2 = a1; ai2 = ai1; a1 = vv; ai1 = vi; }
            else if (vv > a2) { a2 = vv; ai2 = vi; }
        }

        // merge across 16 lanes
        #pragma unroll
        for (int off = 8; off >= 1; off >>= 1) {
            float b1 = __shfl_xor_sync(FULL, a1, off, 16);
            int  bi1 = __shfl_xor_sync(FULL, ai1, off, 16);
            float b2 = __shfl_xor_sync(FULL, a2, off, 16);
            int  bi2 = __shfl_xor_sync(FULL, ai2, off, 16);
            float n1, n2; int ni1, ni2;
            bool btop = (b1 > a1) || (b1 == a1 && bi1 < ai1);
            if (btop) {
                n1 = b1; ni1 = bi1;
                bool asecond = (a1 > b2) || (a1 == b2 && ai1 < bi2);
                if (asecond) { n2 = a1; ni2 = ai1; } else { n2 = b2; ni2 = bi2; }
            } else {
                n1 = a1; ni1 = ai1;
                bool bsecond = (b1 > a2) || (b1 == a2 && bi1 < ai2);
                if (bsecond) { n2 = b1; ni2 = bi1; } else { n2 = a2; ni2 = ai2; }
            }
            a1 = n1; ai1 = ni1; a2 = n2; ai2 = ni2;
        }

        if (tx == 0) {
            out_tw[(size_t)t * 2 + 0] = a1;
            out_tw[(size_t)t * 2 + 1] = a2;
            out_ti[(size_t)t * 2 + 0] = (float)ai1;
            out_ti[(size_t)t * 2 + 1] = (float)ai2;
        }
    }
}

extern "C" void kernel_launch(void* const* d_in, const int* in_sizes, int n_in,
                              void* d_out, int out_size)
{
    const float* x = (const float*)d_in[0];
    const float* W = (const float*)d_in[1];
    const float* b = (const float*)d_in[2];
    float* out = (float*)d_out;
    gating_kernel<<<NT / TPC, 256>>>(x, W, b, out);
}

// round 4
// speedup vs baseline: 1.7156x; 1.7156x over previous
#include <cuda_runtime.h>
#include <cuda_fp16.h>
#include <stdint.h>

#define NT   16384
#define DM   2048
#define NE   64
#define KC   128            // K per chunk
#define NCH  (DM / KC)      // 16 chunks
#define TPC  64             // tokens per CTA
#define WSTR 72             // smem halves stride (16B-aligned rows, ldmatrix conflict-free)
#define LSTR 66             // logits smem float stride

// W split tiles (fp16), k-major [DM][NE]; w0 = h(4096*w), w1 = h((4096w - w0)*4096)
__device__ __align__(16) __half g_w0[DM * NE];
__device__ __align__(16) __half g_w1[DM * NE];

__device__ __forceinline__ uint32_t smem_u32(const void* p) {
    uint32_t a;
    asm("{ .reg .u64 t; cvta.to.shared.u64 t, %1; cvt.u32.u64 %0, t; }" : "=r"(a) : "l"(p));
    return a;
}
__device__ __forceinline__ uint32_t h2u(__half2 h) {
    union { __half2 h; uint32_t u; } c; c.h = h; return c.u;
}
__device__ __forceinline__ void ldmx4t(uint32_t* r, uint32_t addr) {
    asm volatile("ldmatrix.sync.aligned.m8n8.x4.trans.shared.b16 {%0,%1,%2,%3}, [%4];"
                 : "=r"(r[0]), "=r"(r[1]), "=r"(r[2]), "=r"(r[3]) : "r"(addr));
}
__device__ __forceinline__ void mma16816(float* d,
        uint32_t a0, uint32_t a1, uint32_t a2, uint32_t a3,
        uint32_t b0, uint32_t b1) {
    asm volatile("mma.sync.aligned.m16n8k16.row.col.f32.f16.f16.f32 "
                 "{%0,%1,%2,%3},{%4,%5,%6,%7},{%8,%9},{%0,%1,%2,%3};"
                 : "+f"(d[0]), "+f"(d[1]), "+f"(d[2]), "+f"(d[3])
                 : "r"(a0), "r"(a1), "r"(a2), "r"(a3), "r"(b0), "r"(b1));
}

// ---------------- prepass: split W ----------------
__global__ void wsplit(const float* __restrict__ W) {
    int i = blockIdx.x * 256 + threadIdx.x;       // exactly DM*NE threads
    float w = W[i] * 4096.0f;
    __half h0 = __float2half_rn(w);
    float r = (w - __half2float(h0)) * 4096.0f;
    g_w0[i] = h0;
    g_w1[i] = __float2half_rn(r);
}

// ---------------- main kernel ----------------
__global__ __launch_bounds__(128)
void gating_mma(const float* __restrict__ x, const float* __restrict__ bias,
                float* __restrict__ out)
{
    __shared__ __align__(16) __half wsm[2][KC * WSTR];   // ~36.9 KB
    __shared__ float s_bias[NE];

    const int tid  = threadIdx.x;
    const int wid  = tid >> 5;
    const int lane = tid & 31;
    const int ct0  = blockIdx.x * TPC;

    if (tid < NE) s_bias[tid] = bias[tid];

    // A addressing: this thread covers rows gr, gr+8 / cols gc,gc+1 (+8)
    const int gr = lane >> 2;
    const int gc = (lane & 3) * 2;
    const float* xr0 = x + (size_t)(ct0 + wid * 16 + gr) * DM + gc;
    const float* xr1 = xr0 + 8 * DM;

    // ldmatrix per-lane offset (halves -> bytes)
    const int lm_k = (lane & 7) + ((lane >> 3) & 1) * 8;
    const int lm_n = (lane >> 4) * 8;
    const uint32_t lm_off = (uint32_t)(lm_k * WSTR + lm_n) * 2;
    const uint32_t w0b = smem_u32(&wsm[0][0]) + lm_off;
    const uint32_t w1b = smem_u32(&wsm[1][0]) + lm_off;

    float acc1[8][4] = {}, acc2[8][4] = {};
    float out1[8][4] = {}, out2[8][4] = {};

    for (int c = 0; c < NCH; ++c) {
        // ---- stage W chunk (both splits) ----
        const uint4* g0 = (const uint4*)g_w0 + (size_t)c * (KC * NE / 8);
        const uint4* g1 = (const uint4*)g_w1 + (size_t)c * (KC * NE / 8);
        #pragma unroll
        for (int j = 0; j < 8; j++) {
            int idx = j * 128 + tid;
            int r = idx >> 3, q = idx & 7;
            uint4 v0 = g0[idx];
            uint4 v1 = g1[idx];
            *(uint4*)((char*)&wsm[0][0] + (r * WSTR + q * 8) * 2) = v0;
            *(uint4*)((char*)&wsm[1][0] + (r * WSTR + q * 8) * 2) = v1;
        }
        __syncthreads();

        const int colc = c * KC;
        #pragma unroll
        for (int ks = 0; ks < KC / 16; ++ks) {
            const int col = colc + ks * 16;
            // ---- A: load fp32, 2-split to fp16 ----
            float2 v00 = *(const float2*)(xr0 + col);
            float2 v10 = *(const float2*)(xr1 + col);
            float2 v01 = *(const float2*)(xr0 + col + 8);
            float2 v11 = *(const float2*)(xr1 + col + 8);

            uint32_t A0[4], A1[4];
            {
                float2 v[4] = { v00, v10, v01, v11 };
                #pragma unroll
                for (int q = 0; q < 4; q++) {
                    __half2 h0 = __float22half2_rn(v[q]);
                    float2 lo = __half22float2(h0);
                    float2 rr = make_float2((v[q].x - lo.x) * 4096.0f,
                                            (v[q].y - lo.y) * 4096.0f);
                    A0[q] = h2u(h0);
                    A1[q] = h2u(__float22half2_rn(rr));
                }
            }

            // ---- B tiles + MMA, 4 ntile-pairs ----
            const uint32_t koff = (uint32_t)(ks * 16 * WSTR) * 2;
            #pragma unroll
            for (int p = 0; p < 4; p++) {
                uint32_t b0[4], b1[4];
                const uint32_t poff = koff + (uint32_t)(p * 16) * 2;
                ldmx4t(b0, w0b + poff);
                ldmx4t(b1, w1b + poff);
                // ntile 2p
                mma16816(acc1[2*p],   A0[0],A0[1],A0[2],A0[3], b0[0], b0[1]);
                mma16816(acc2[2*p],   A0[0],A0[1],A0[2],A0[3], b1[0], b1[1]);
                mma16816(acc2[2*p],   A1[0],A1[1],A1[2],A1[3], b0[0], b0[1]);
                // ntile 2p+1
                mma16816(acc1[2*p+1], A0[0],A0[1],A0[2],A0[3], b0[2], b0[3]);
                mma16816(acc2[2*p+1], A0[0],A0[1],A0[2],A0[3], b1[2], b1[3]);
                mma16816(acc2[2*p+1], A1[0],A1[1],A1[2],A1[3], b0[2], b0[3]);
            }
        }
        __syncthreads();

        // segment the fp32 accumulation (reduce rounding growth)
        if ((c & 3) == 3) {
            #pragma unroll
            for (int nt = 0; nt < 8; nt++)
                #pragma unroll
                for (int i = 0; i < 4; i++) {
                    out1[nt][i] += acc1[nt][i]; acc1[nt][i] = 0.0f;
                    out2[nt][i] += acc2[nt][i]; acc2[nt][i] = 0.0f;
                }
        }
    }

    // ---- logits to SMEM (alias wsm) ----
    // logit = ((out1 + 2^-12 * out2)) * 2^-12   [x*w = 2^-12 * x*w', w' = 4096w]
    float* slog = (float*)&wsm[0][0];
    const float S2 = 1.0f / 4096.0f;          // 2^-12
    const int tl = wid * 16 + gr;
    #pragma unroll
    for (int nt = 0; nt < 8; nt++) {
        const int cc = nt * 8 + gc;
        float l00 = (out1[nt][0] + S2 * out2[nt][0]) * S2;
        float l01 = (out1[nt][1] + S2 * out2[nt][1]) * S2;
        float l10 = (out1[nt][2] + S2 * out2[nt][2]) * S2;
        float l11 = (out1[nt][3] + S2 * out2[nt][3]) * S2;
        *(float2*)&slog[tl * LSTR + cc]       = make_float2(l00, l01);
        *(float2*)&slog[(tl + 8) * LSTR + cc] = make_float2(l10, l11);
    }
    __syncthreads();

    // ---- per-token softmax + top-2 (threads 0..63) ----
    if (tid < TPC) {
        const int t = ct0 + tid;
        float lg[NE];
        #pragma unroll
        for (int e = 0; e < NE; e++) lg[e] = slog[tid * LSTR + e] + s_bias[e];

        float m = lg[0];
        #pragma unroll
        for (int e = 1; e < NE; e++) m = fmaxf(m, lg[e]);

        float l1 = lg[0], l2 = -3.4e38f; int i1 = 0, i2 = 0;
        #pragma unroll
        for (int e = 1; e < NE; e++) {
            float v = lg[e];
            if (v > l1)      { l2 = l1; i2 = i1; l1 = v; i1 = e; }
            else if (v > l2) { l2 = v;  i2 = e; }
        }

        float s = 0.0f;
        #pragma unroll
        for (int e = 0; e < NE; e++) { float w = __expf(lg[e] - m); lg[e] = w; s += w; }
        float inv = 1.0f / s;

        float* out_w = out + (size_t)NT * 4 + (size_t)t * NE;
        #pragma unroll
        for (int e4 = 0; e4 < NE / 4; e4++) {
            float4 o4 = make_float4(lg[e4*4] * inv, lg[e4*4+1] * inv,
                                    lg[e4*4+2] * inv, lg[e4*4+3] * inv);
            *(float4*)(out_w + e4 * 4) = o4;
        }
        float w1 = __expf(l1 - m) * inv;
        float w2 = __expf(l2 - m) * inv;
        *(float2*)(out + (size_t)t * 2)                  = make_float2(w1, w2);
        *(float2*)(out + (size_t)NT * 2 + (size_t)t * 2) = make_float2((float)i1, (float)i2);
    }
}

extern "C" void kernel_launch(void* const* d_in, const int* in_sizes, int n_in,
                              void* d_out, int out_size)
{
    const float* x = (const float*)d_in[0];
    const float* W = (const float*)d_in[1];
    const float* b = (const float*)d_in[2];
    float* out = (float*)d_out;

    wsplit<<<(DM * NE) / 256, 256>>>(W);
    gating_mma<<<NT / TPC, 128>>>(x, b, out);
}

// round 5
// speedup vs baseline: 2.3554x; 1.3729x over previous
#include <cuda_runtime.h>
#include <cuda_fp16.h>
#include <stdint.h>

#define NT    16384
#define DM    2048
#define NE    64
#define KC    64            // K per staged chunk
#define NCHG  16            // chunks per K-group (2 groups x 16 x 64 = 2048)
#define TPC   64            // tokens per CTA
#define WSTR  72            // smem halves stride
#define LSTR  66            // partial-logits smem float stride

// W split (fp16), k-major [DM][NE]; w0 = h(4096*w), w1 = h((4096w - w0)*4096)
__device__ __align__(16) __half g_w0[DM * NE];
__device__ __align__(16) __half g_w1[DM * NE];

#define SM_STAGE_BYTES (2 * 2 * KC * WSTR * 2)   // 36864
#define SM_PART_BYTES  (2 * TPC * LSTR * 4)      // 33792

__device__ __forceinline__ uint32_t smem_u32(const void* p) {
    uint32_t a;
    asm("{ .reg .u64 t; cvta.to.shared.u64 t, %1; cvt.u32.u64 %0, t; }" : "=r"(a) : "l"(p));
    return a;
}
__device__ __forceinline__ uint32_t h2u(__half2 h) {
    union { __half2 h; uint32_t u; } c; c.h = h; return c.u;
}
__device__ __forceinline__ void ldmx4t(uint32_t* r, uint32_t addr) {
    asm volatile("ldmatrix.sync.aligned.m8n8.x4.trans.shared.b16 {%0,%1,%2,%3}, [%4];"
                 : "=r"(r[0]), "=r"(r[1]), "=r"(r[2]), "=r"(r[3]) : "r"(addr));
}
__device__ __forceinline__ void mma16816(float* d,
        const uint32_t* a, uint32_t b0, uint32_t b1) {
    asm volatile("mma.sync.aligned.m16n8k16.row.col.f32.f16.f16.f32 "
                 "{%0,%1,%2,%3},{%4,%5,%6,%7},{%8,%9},{%0,%1,%2,%3};"
                 : "+f"(d[0]), "+f"(d[1]), "+f"(d[2]), "+f"(d[3])
                 : "r"(a[0]), "r"(a[1]), "r"(a[2]), "r"(a[3]), "r"(b0), "r"(b1));
}

// ---------------- prepass: split W ----------------
__global__ void wsplit(const float* __restrict__ W) {
    int i = blockIdx.x * 256 + threadIdx.x;
    float w = W[i] * 4096.0f;
    __half h0 = __float2half_rn(w);
    float r = (w - __half2float(h0)) * 4096.0f;
    g_w0[i] = h0;
    g_w1[i] = __float2half_rn(r);
}

// ---------------- main kernel ----------------
__global__ __launch_bounds__(256, 2)
void gating_mma(const float* __restrict__ x, const float* __restrict__ bias,
                float* __restrict__ out)
{
    __shared__ __align__(16) uint8_t smraw[SM_STAGE_BYTES];  // stage/part union
    __shared__ float s_bias[NE];

    const int tid  = threadIdx.x;
    const int wid  = tid >> 5;
    const int lane = tid & 31;
    const int wg   = wid >> 2;        // K group 0/1
    const int w4   = wid & 3;         // token tile within CTA
    const int ct0  = blockIdx.x * TPC;

    if (tid < NE) s_bias[tid] = bias[tid];

    const int gr = lane >> 2;
    const int gc = (lane & 3) * 2;
    const float* xr0 = x + (size_t)(ct0 + w4 * 16 + gr) * DM + gc;
    const float* xr1 = xr0 + 8 * DM;

    // ldmatrix per-lane offset
    const int lm_k = (lane & 7) + ((lane >> 3) & 1) * 8;
    const int lm_n = (lane >> 4) * 8;
    const uint32_t lm_off = (uint32_t)(lm_k * WSTR + lm_n) * 2;
    const uint32_t smb = smem_u32(smraw);
    const uint32_t w0b = smb + (uint32_t)(wg * 2 * KC * WSTR) * 2 + lm_off;
    const uint32_t w1b = w0b + (uint32_t)(KC * WSTR) * 2;

    float acc1[8][4] = {}, acc2[8][4] = {};

    const int kg0 = wg * NCHG;   // this group's first chunk

    for (int c = 0; c < NCHG; ++c) {
        // ---- stage both groups' W chunks (all 256 threads, 8 x uint4 each) ----
        #pragma unroll
        for (int j = 0; j < 8; j++) {
            int idx = j * 256 + tid;              // 0..2047
            int g = idx >> 10;
            int s = (idx >> 9) & 1;
            int r = (idx >> 3) & 63;
            int q = idx & 7;
            const uint4* gp = s ? (const uint4*)g_w1 : (const uint4*)g_w0;
            uint4 v = gp[(size_t)((g * NCHG + c) * KC + r) * 8 + q];
            *(uint4*)(smraw + ((g * 2 + s) * KC * WSTR + r * WSTR + q * 8) * 2) = v;
        }
        __syncthreads();

        const int colc = (kg0 + c) * KC;
        #pragma unroll
        for (int ks = 0; ks < KC / 16; ++ks) {
            const int col = colc + ks * 16;
            float2 v[4];
            v[0] = *(const float2*)(xr0 + col);
            v[1] = *(const float2*)(xr1 + col);
            v[2] = *(const float2*)(xr0 + col + 8);
            v[3] = *(const float2*)(xr1 + col + 8);

            uint32_t A0[4], A1[4];
            #pragma unroll
            for (int q = 0; q < 4; q++) {
                __half2 h0 = __float22half2_rn(v[q]);
                float2 lo = __half22float2(h0);
                float2 rr = make_float2((v[q].x - lo.x) * 4096.0f,
                                        (v[q].y - lo.y) * 4096.0f);
                A0[q] = h2u(h0);
                A1[q] = h2u(__float22half2_rn(rr));
            }

            const uint32_t koff = (uint32_t)(ks * 16 * WSTR) * 2;
            #pragma unroll
            for (int p = 0; p < 4; p++) {
                uint32_t b0[4], b1[4];
                const uint32_t poff = koff + (uint32_t)(p * 16) * 2;
                ldmx4t(b0, w0b + poff);
                ldmx4t(b1, w1b + poff);
                // interleave so same-acc MMAs are >=2 apart
                mma16816(acc1[2*p],   A0, b0[0], b0[1]);
                mma16816(acc1[2*p+1], A0, b0[2], b0[3]);
                mma16816(acc2[2*p],   A0, b1[0], b1[1]);
                mma16816(acc2[2*p+1], A0, b1[2], b1[3]);
                mma16816(acc2[2*p],   A1, b0[0], b0[1]);
                mma16816(acc2[2*p+1], A1, b0[2], b0[3]);
            }
        }
        __syncthreads();
    }

    // ---- partial logits to SMEM: part[g][token][expert] ----
    float* part = (float*)smraw;
    const float S2 = 1.0f / 4096.0f;   // 2^-12
    const int tl = w4 * 16 + gr;
    #pragma unroll
    for (int nt = 0; nt < 8; nt++) {
        const int cc = nt * 8 + gc;
        float p00 = acc1[nt][0] + S2 * acc2[nt][0];
        float p01 = acc1[nt][1] + S2 * acc2[nt][1];
        float p10 = acc1[nt][2] + S2 * acc2[nt][2];
        float p11 = acc1[nt][3] + S2 * acc2[nt][3];
        *(float2*)&part[(wg * TPC + tl)     * LSTR + cc] = make_float2(p00, p01);
        *(float2*)&part[(wg * TPC + tl + 8) * LSTR + cc] = make_float2(p10, p11);
    }
    __syncthreads();

    // ---- per-token combine + softmax + top-2 (threads 0..63) ----
    if (tid < TPC) {
        const int t = ct0 + tid;
        float lg[NE];
        #pragma unroll
        for (int e = 0; e < NE; e++)
            lg[e] = (part[tid * LSTR + e] + part[(TPC + tid) * LSTR + e]) * S2 + s_bias[e];

        float m = lg[0];
        #pragma unroll
        for (int e = 1; e < NE; e++) m = fmaxf(m, lg[e]);

        float l1 = lg[0], l2 = -3.4e38f; int i1 = 0, i2 = 0;
        #pragma unroll
        for (int e = 1; e < NE; e++) {
            float vv = lg[e];
            if (vv > l1)      { l2 = l1; i2 = i1; l1 = vv; i1 = e; }
            else if (vv > l2) { l2 = vv; i2 = e; }
        }

        float s = 0.0f;
        #pragma unroll
        for (int e = 0; e < NE; e++) { float w = __expf(lg[e] - m); lg[e] = w; s += w; }
        float inv = 1.0f / s;

        float* out_w = out + (size_t)NT * 4 + (size_t)t * NE;
        #pragma unroll
        for (int e4 = 0; e4 < NE / 4; e4++) {
            float4 o4 = make_float4(lg[e4*4] * inv, lg[e4*4+1] * inv,
                                    lg[e4*4+2] * inv, lg[e4*4+3] * inv);
            *(float4*)(out_w + e4 * 4) = o4;
        }
        float w1 = __expf(l1 - m) * inv;
        float w2 = __expf(l2 - m) * inv;
        *(float2*)(out + (size_t)t * 2)                  = make_float2(w1, w2);
        *(float2*)(out + (size_t)NT * 2 + (size_t)t * 2) = make_float2((float)i1, (float)i2);
    }
}

extern "C" void kernel_launch(void* const* d_in, const int* in_sizes, int n_in,
                              void* d_out, int out_size)
{
    const float* x = (const float*)d_in[0];
    const float* W = (const float*)d_in[1];
    const float* b = (const float*)d_in[2];
    float* out = (float*)d_out;

    wsplit<<<(DM * NE) / 256, 256>>>(W);
    gating_mma<<<NT / TPC, 256>>>(x, b, out);
}

// round 6
// speedup vs baseline: 2.5801x; 1.0954x over previous
#include <cuda_runtime.h>
#include <cuda_fp16.h>
#include <stdint.h>

#define NT    16384
#define DM    2048
#define NE    64
#define KC    64            // K per staged chunk
#define NCHG  16            // chunks per K-group (2 groups x 16 x 64 = 2048)
#define TPC   64            // tokens per CTA
#define WSTR  72            // smem halves stride
#define LSTR  66            // partial-logits smem float stride

#define STAGE_BYTES (2 * 2 * KC * WSTR * 2)   // 36864 per buffer
#define SMEM_DYN    (2 * STAGE_BYTES)         // 73728

// W split (fp16), k-major [DM][NE]; w0 = h(4096*w), w1 = h((4096w - w0)*4096)
__device__ __align__(16) __half g_w0[DM * NE];
__device__ __align__(16) __half g_w1[DM * NE];

__device__ __forceinline__ uint32_t smem_u32(const void* p) {
    uint32_t a;
    asm("{ .reg .u64 t; cvta.to.shared.u64 t, %1; cvt.u32.u64 %0, t; }" : "=r"(a) : "l"(p));
    return a;
}
__device__ __forceinline__ uint32_t h2u(__half2 h) {
    union { __half2 h; uint32_t u; } c; c.h = h; return c.u;
}
__device__ __forceinline__ void cpa16(uint32_t dst, const void* src) {
    asm volatile("cp.async.cg.shared.global [%0], [%1], 16;" :: "r"(dst), "l"(src));
}
__device__ __forceinline__ void ldmx4t(uint32_t* r, uint32_t addr) {
    asm volatile("ldmatrix.sync.aligned.m8n8.x4.trans.shared.b16 {%0,%1,%2,%3}, [%4];"
                 : "=r"(r[0]), "=r"(r[1]), "=r"(r[2]), "=r"(r[3]) : "r"(addr));
}
__device__ __forceinline__ void mma16816(float* d,
        const uint32_t* a, uint32_t b0, uint32_t b1) {
    asm volatile("mma.sync.aligned.m16n8k16.row.col.f32.f16.f16.f32 "
                 "{%0,%1,%2,%3},{%4,%5,%6,%7},{%8,%9},{%0,%1,%2,%3};"
                 : "+f"(d[0]), "+f"(d[1]), "+f"(d[2]), "+f"(d[3])
                 : "r"(a[0]), "r"(a[1]), "r"(a[2]), "r"(a[3]), "r"(b0), "r"(b1));
}

// ---------------- prepass: split W ----------------
__global__ void wsplit(const float* __restrict__ W) {
    int i = blockIdx.x * 256 + threadIdx.x;
    float w = W[i] * 4096.0f;
    __half h0 = __float2half_rn(w);
    float r = (w - __half2float(h0)) * 4096.0f;
    g_w0[i] = h0;
    g_w1[i] = __float2half_rn(r);
}

// ---------------- main kernel ----------------
__global__ __launch_bounds__(256, 2)
void gating_mma(const float* __restrict__ x, const float* __restrict__ bias,
                float* __restrict__ out)
{
    extern __shared__ __align__(16) uint8_t smraw[];   // 2 stage buffers / partials
    __shared__ float s_bias[NE];

    const int tid  = threadIdx.x;
    const int wid  = tid >> 5;
    const int lane = tid & 31;
    const int wg   = wid >> 2;        // K group 0/1
    const int w4   = wid & 3;         // token tile within CTA
    const int ct0  = blockIdx.x * TPC;

    if (tid < NE) s_bias[tid] = bias[tid];

    const int gr = lane >> 2;
    const int gc = (lane & 3) * 2;
    const float* xr0 = x + (size_t)(ct0 + w4 * 16 + gr) * DM + gc;
    const float* xr1 = xr0 + 8 * DM;

    // ldmatrix per-lane offset
    const int lm_k = (lane & 7) + ((lane >> 3) & 1) * 8;
    const int lm_n = (lane >> 4) * 8;
    const uint32_t lm_off = (uint32_t)(lm_k * WSTR + lm_n) * 2;
    const uint32_t smb = smem_u32(smraw);
    const uint32_t w0b = smb + (uint32_t)(wg * 2 * KC * WSTR) * 2 + lm_off;
    const uint32_t w1b = w0b + (uint32_t)(KC * WSTR) * 2;

    // staging: per-thread j-invariant pieces
    // idx = j*256 + tid: g = idx>>10, s = (idx>>9)&1, r = (idx>>3)&63, q = idx&7
    const int kg0 = wg * NCHG;

    auto stage = [&](int c, int buf) {
        #pragma unroll
        for (int j = 0; j < 8; j++) {
            int idx = j * 256 + tid;
            int g = idx >> 10;
            int s = (idx >> 9) & 1;
            int r = (idx >> 3) & 63;
            int q = idx & 7;
            const uint4* gp = s ? (const uint4*)g_w1 : (const uint4*)g_w0;
            const uint4* src = gp + (size_t)((g * NCHG + c) * KC + r) * 8 + q;
            uint32_t dst = smb + buf * STAGE_BYTES
                         + (uint32_t)(((g * 2 + s) * KC + r) * WSTR + q * 8) * 2;
            cpa16(dst, src);
        }
        asm volatile("cp.async.commit_group;" ::: "memory");
    };

    float acc1[8][4] = {}, acc2[8][4] = {};

    stage(0, 0);

    // preload x for first ks
    float2 xc[4];
    {
        const int col = kg0 * KC;
        xc[0] = *(const float2*)(xr0 + col);
        xc[1] = *(const float2*)(xr1 + col);
        xc[2] = *(const float2*)(xr0 + col + 8);
        xc[3] = *(const float2*)(xr1 + col + 8);
    }

    int buf = 0;
    for (int c = 0; c < NCHG; ++c) {
        asm volatile("cp.async.wait_group 0;" ::: "memory");
        __syncthreads();
        if (c + 1 < NCHG) stage(c + 1, buf ^ 1);

        const uint32_t wb0 = w0b + buf * STAGE_BYTES;
        const uint32_t wb1 = w1b + buf * STAGE_BYTES;

        #pragma unroll
        for (int ks = 0; ks < KC / 16; ++ks) {
            // prefetch next x (next ks, or next chunk's ks0)
            float2 xn[4];
            const bool more = (ks < 3) || (c + 1 < NCHG);
            if (more) {
                const int ncol = (ks < 3) ? (kg0 + c) * KC + (ks + 1) * 16
                                          : (kg0 + c + 1) * KC;
                xn[0] = *(const float2*)(xr0 + ncol);
                xn[1] = *(const float2*)(xr1 + ncol);
                xn[2] = *(const float2*)(xr0 + ncol + 8);
                xn[3] = *(const float2*)(xr1 + ncol + 8);
            }

            uint32_t A0[4], A1[4];
            #pragma unroll
            for (int q = 0; q < 4; q++) {
                __half2 h0 = __float22half2_rn(xc[q]);
                float2 lo = __half22float2(h0);
                float2 rr = make_float2((xc[q].x - lo.x) * 4096.0f,
                                        (xc[q].y - lo.y) * 4096.0f);
                A0[q] = h2u(h0);
                A1[q] = h2u(__float22half2_rn(rr));
            }

            const uint32_t koff = (uint32_t)(ks * 16 * WSTR) * 2;
            #pragma unroll
            for (int p = 0; p < 4; p++) {
                uint32_t b0[4], b1[4];
                const uint32_t poff = koff + (uint32_t)(p * 16) * 2;
                ldmx4t(b0, wb0 + poff);
                ldmx4t(b1, wb1 + poff);
                mma16816(acc1[2*p],   A0, b0[0], b0[1]);
                mma16816(acc1[2*p+1], A0, b0[2], b0[3]);
                mma16816(acc2[2*p],   A0, b1[0], b1[1]);
                mma16816(acc2[2*p+1], A0, b1[2], b1[3]);
                mma16816(acc2[2*p],   A1, b0[0], b0[1]);
                mma16816(acc2[2*p+1], A1, b0[2], b0[3]);
            }

            #pragma unroll
            for (int q = 0; q < 4; q++) xc[q] = xn[q];
        }
        __syncthreads();
        buf ^= 1;
    }

    // ---- partial logits to SMEM: part[g][token][expert] ----
    float* part = (float*)smraw;
    const float S2 = 1.0f / 4096.0f;   // 2^-12
    const int tl = w4 * 16 + gr;
    #pragma unroll
    for (int nt = 0; nt < 8; nt++) {
        const int cc = nt * 8 + gc;
        float p00 = acc1[nt][0] + S2 * acc2[nt][0];
        float p01 = acc1[nt][1] + S2 * acc2[nt][1];
        float p10 = acc1[nt][2] + S2 * acc2[nt][2];
        float p11 = acc1[nt][3] + S2 * acc2[nt][3];
        *(float2*)&part[(wg * TPC + tl)     * LSTR + cc] = make_float2(p00, p01);
        *(float2*)&part[(wg * TPC + tl + 8) * LSTR + cc] = make_float2(p10, p11);
    }
    __syncthreads();

    // ---- per-token combine + softmax + top-2 (threads 0..63) ----
    if (tid < TPC) {
        const int t = ct0 + tid;
        float lg[NE];
        #pragma unroll
        for (int e = 0; e < NE; e++)
            lg[e] = (part[tid * LSTR + e] + part[(TPC + tid) * LSTR + e]) * S2 + s_bias[e];

        float m = lg[0];
        #pragma unroll
        for (int e = 1; e < NE; e++) m = fmaxf(m, lg[e]);

        float l1 = lg[0], l2 = -3.4e38f; int i1 = 0, i2 = 0;
        #pragma unroll
        for (int e = 1; e < NE; e++) {
            float vv = lg[e];
            if (vv > l1)      { l2 = l1; i2 = i1; l1 = vv; i1 = e; }
            else if (vv > l2) { l2 = vv; i2 = e; }
        }

        float s = 0.0f;
        #pragma unroll
        for (int e = 0; e < NE; e++) { float w = __expf(lg[e] - m); lg[e] = w; s += w; }
        float inv = 1.0f / s;

        float* out_w = out + (size_t)NT * 4 + (size_t)t * NE;
        #pragma unroll
        for (int e4 = 0; e4 < NE / 4; e4++) {
            float4 o4 = make_float4(lg[e4*4] * inv, lg[e4*4+1] * inv,
                                    lg[e4*4+2] * inv, lg[e4*4+3] * inv);
            *(float4*)(out_w + e4 * 4) = o4;
        }
        float w1 = __expf(l1 - m) * inv;
        float w2 = __expf(l2 - m) * inv;
        *(float2*)(out + (size_t)t * 2)                  = make_float2(w1, w2);
        *(float2*)(out + (size_t)NT * 2 + (size_t)t * 2) = make_float2((float)i1, (float)i2);
    }
}

extern "C" void kernel_launch(void* const* d_in, const int* in_sizes, int n_in,
                              void* d_out, int out_size)
{
    const float* x = (const float*)d_in[0];
    const float* W = (const float*)d_in[1];
    const float* b = (const float*)d_in[2];
    float* out = (float*)d_out;

    wsplit<<<(DM * NE) / 256, 256>>>(W);

    cudaFuncSetAttribute(gating_mma, cudaFuncAttributeMaxDynamicSharedMemorySize, SMEM_DYN);
    gating_mma<<<NT / TPC, 256, SMEM_DYN>>>(x, b, out);
}